// round 3
// baseline (speedup 1.0000x reference)
#include <cuda_runtime.h>

namespace {

constexpr int NS      = 512;   // matrix dim (S = K = O = 512)
constexpr int TM      = 64;    // block tile rows
constexpr int TN      = 64;    // block tile cols
constexpr int TK      = 32;    // k chunk
constexpr int NCHUNK  = NS / TK;  // 16
constexpr int THREADS = 256;
constexpr int APAD    = 4;     // As row pad (row stride 36 floats: keeps 16B align, kills conflicts)

__global__ __launch_bounds__(THREADS, 1)
void fuzzy_compose_kernel(const float* __restrict__ t, float* __restrict__ out)
{
    __shared__ float As[TM][TK + APAD];  // [m][k], row stride 36 floats
    __shared__ float Bs[TK][TN];         // [k][n]

    const int comp = blockIdx.z;              // 0: t0∘t0, 1: t0∘t1
    const int bm   = blockIdx.y * TM;
    const int bn   = blockIdx.x * TN;

    const float* __restrict__ A = t;                        // t0 (left operand, both rules)
    const float* __restrict__ B = t + comp * (NS * NS);     // t[comp] (right operand)

    const int tid = threadIdx.x;
    const int tx  = tid & 15;       // n direction (16)
    const int ty  = tid >> 4;       // m direction (16)
    const int m0  = ty * 4;
    const int n0  = tx * 4;

    // ---- per-thread load indices (float4 granularity) ----
    // A chunk: 64 rows x 32 cols = 512 float4; idx = tid + 256*i
    const int ar0 = tid >> 3;            const int ac0 = (tid & 7) * 4;
    const int ar1 = (tid + 256) >> 3;    const int ac1 = ((tid + 256) & 7) * 4;
    // B chunk: 32 rows x 64 cols = 512 float4
    const int br0 = tid >> 4;            const int bc0 = (tid & 15) * 4;
    const int br1 = (tid + 256) >> 4;    const int bc1 = ((tid + 256) & 15) * 4;

    float acc[4][4];
#pragma unroll
    for (int i = 0; i < 4; ++i)
#pragma unroll
        for (int j = 0; j < 4; ++j) acc[i][j] = 0.0f;   // inputs are in [0,1): 0 is a valid identity for max

    // ---- prefetch chunk 0 into registers ----
    float4 ra0 = *reinterpret_cast<const float4*>(&A[(bm + ar0) * NS + ac0]);
    float4 ra1 = *reinterpret_cast<const float4*>(&A[(bm + ar1) * NS + ac1]);
    float4 rb0 = *reinterpret_cast<const float4*>(&B[(br0) * NS + bn + bc0]);
    float4 rb1 = *reinterpret_cast<const float4*>(&B[(br1) * NS + bn + bc1]);

    for (int c = 0; c < NCHUNK; ++c) {
        __syncthreads();   // previous chunk's compute done (no-op on first iter)
        *reinterpret_cast<float4*>(&As[ar0][ac0]) = ra0;
        *reinterpret_cast<float4*>(&As[ar1][ac1]) = ra1;
        *reinterpret_cast<float4*>(&Bs[br0][bc0]) = rb0;
        *reinterpret_cast<float4*>(&Bs[br1][bc1]) = rb1;
        __syncthreads();   // tiles visible

        if (c + 1 < NCHUNK) {
            const int kn = (c + 1) * TK;
            ra0 = *reinterpret_cast<const float4*>(&A[(bm + ar0) * NS + kn + ac0]);
            ra1 = *reinterpret_cast<const float4*>(&A[(bm + ar1) * NS + kn + ac1]);
            rb0 = *reinterpret_cast<const float4*>(&B[(kn + br0) * NS + bn + bc0]);
            rb1 = *reinterpret_cast<const float4*>(&B[(kn + br1) * NS + bn + bc1]);
        }

#pragma unroll
        for (int kk = 0; kk < TK; ++kk) {
            const float a0 = As[m0 + 0][kk];
            const float a1 = As[m0 + 1][kk];
            const float a2 = As[m0 + 2][kk];
            const float a3 = As[m0 + 3][kk];
            const float4 b = *reinterpret_cast<const float4*>(&Bs[kk][n0]);

            acc[0][0] = fmaxf(acc[0][0], fminf(a0, b.x));
            acc[0][1] = fmaxf(acc[0][1], fminf(a0, b.y));
            acc[0][2] = fmaxf(acc[0][2], fminf(a0, b.z));
            acc[0][3] = fmaxf(acc[0][3], fminf(a0, b.w));

            acc[1][0] = fmaxf(acc[1][0], fminf(a1, b.x));
            acc[1][1] = fmaxf(acc[1][1], fminf(a1, b.y));
            acc[1][2] = fmaxf(acc[1][2], fminf(a1, b.z));
            acc[1][3] = fmaxf(acc[1][3], fminf(a1, b.w));

            acc[2][0] = fmaxf(acc[2][0], fminf(a2, b.x));
            acc[2][1] = fmaxf(acc[2][1], fminf(a2, b.y));
            acc[2][2] = fmaxf(acc[2][2], fminf(a2, b.z));
            acc[2][3] = fmaxf(acc[2][3], fminf(a2, b.w));

            acc[3][0] = fmaxf(acc[3][0], fminf(a3, b.x));
            acc[3][1] = fmaxf(acc[3][1], fminf(a3, b.y));
            acc[3][2] = fmaxf(acc[3][2], fminf(a3, b.z));
            acc[3][3] = fmaxf(acc[3][3], fminf(a3, b.w));
        }
    }

    // ---- epilogue: out = t + num*(1 - t), with t = t[comp] (== B panel) ----
    float* __restrict__ O = out + comp * (NS * NS);
#pragma unroll
    for (int i = 0; i < 4; ++i) {
        const int row = bm + m0 + i;
        const float4 tv = *reinterpret_cast<const float4*>(&B[row * NS + bn + n0]);
        float4 r;
        r.x = tv.x + acc[i][0] * (1.0f - tv.x);
        r.y = tv.y + acc[i][1] * (1.0f - tv.y);
        r.z = tv.z + acc[i][2] * (1.0f - tv.z);
        r.w = tv.w + acc[i][3] * (1.0f - tv.w);
        *reinterpret_cast<float4*>(&O[row * NS + bn + n0]) = r;
    }
}

} // namespace

extern "C" void kernel_launch(void* const* d_in, const int* in_sizes, int n_in,
                              void* d_out, int out_size)
{
    (void)in_sizes; (void)n_in; (void)out_size;
    const float* t = reinterpret_cast<const float*>(d_in[0]);
    float* out     = reinterpret_cast<float*>(d_out);

    dim3 grid(NS / TN, NS / TM, 2);   // 8 x 8 x 2 = 128 blocks
    fuzzy_compose_kernel<<<grid, THREADS>>>(t, out);
}

// round 5
// speedup vs baseline: 1.6465x; 1.6465x over previous
#include <cuda_runtime.h>
#include <cuda_fp16.h>

namespace {

constexpr int NS      = 512;     // matrix dim (S = K = O = 512)
constexpr int TM      = 64;      // block tile rows
constexpr int TN      = 64;      // block tile cols
constexpr int TK      = 32;      // k chunk (floats); 16 half2 pairs
constexpr int NCHUNK  = NS / TK; // 16
constexpr int THREADS = 256;
constexpr int KP      = TK / 2;  // 16 k-pairs per chunk
constexpr int APAD    = 1;       // As2 row pad (half2 units): warp's 2 rows -> distinct banks

__global__ __launch_bounds__(THREADS, 1)
void fuzzy_compose_h2_kernel(const float* __restrict__ t, float* __restrict__ out)
{
    // A tile: [m][kpair] half2 = (A[m,2kp], A[m,2kp+1])
    __shared__ __half2 As2[TM][KP + APAD];   // 64 x 17 half2
    // B tile: [kpair][n] half2 = (B[2kp,n], B[2kp+1,n])
    __shared__ __half2 Bs2[KP][TN];          // 16 x 64 half2

    const int comp = blockIdx.z;             // 0: t0∘t0, 1: t0∘t1
    const int bm   = blockIdx.y * TM;
    const int bn   = blockIdx.x * TN;

    const float* __restrict__ A = t;                     // t0 (left operand of both rules)
    const float* __restrict__ B = t + comp * (NS * NS);  // t[comp] (right operand)

    const int tid = threadIdx.x;
    const int tx  = tid & 15;       // n direction (16)
    const int ty  = tid >> 4;       // m direction (16)
    const int m0  = ty * 4;
    const int n0  = tx * 4;         // in half2 columns == float columns

    // ---- loader indices ----
    // A chunk: 64 rows x 32 floats = 512 float4; 2 per thread
    const int ar0 = tid >> 3;            const int ac0 = (tid & 7) * 4;
    const int ar1 = (tid + 256) >> 3;    const int ac1 = ((tid + 256) & 7) * 4;
    // B chunk: 32 rows x 64 floats; each thread owns one k-pair x 4 n-cols
    const int bkp = tid >> 4;            // k-pair 0..15
    const int bnc = (tid & 15) * 4;      // n col 0..60

    __half2 acc[4][4];
    const __half2 h2zero = __float2half2_rn(0.0f);  // inputs in [0,1): 0 is a max-identity
#pragma unroll
    for (int i = 0; i < 4; ++i)
#pragma unroll
        for (int j = 0; j < 4; ++j) acc[i][j] = h2zero;

    // ---- prefetch chunk 0 into registers (fp32) ----
    float4 ra0 = *reinterpret_cast<const float4*>(&A[(bm + ar0) * NS + ac0]);
    float4 ra1 = *reinterpret_cast<const float4*>(&A[(bm + ar1) * NS + ac1]);
    float4 rb0 = *reinterpret_cast<const float4*>(&B[(2 * bkp    ) * NS + bn + bnc]);
    float4 rb1 = *reinterpret_cast<const float4*>(&B[(2 * bkp + 1) * NS + bn + bnc]);

    for (int c = 0; c < NCHUNK; ++c) {
        __syncthreads();   // previous chunk's compute done

        // A: float4 covers k..k+3 -> two k-adjacent half2
        {
            __half2 h0 = __floats2half2_rn(ra0.x, ra0.y);
            __half2 h1 = __floats2half2_rn(ra0.z, ra0.w);
            As2[ar0][ac0 / 2]     = h0;
            As2[ar0][ac0 / 2 + 1] = h1;
            __half2 g0 = __floats2half2_rn(ra1.x, ra1.y);
            __half2 g1 = __floats2half2_rn(ra1.z, ra1.w);
            As2[ar1][ac1 / 2]     = g0;
            As2[ar1][ac1 / 2 + 1] = g1;
        }
        // B: interleave even/odd k rows into (k,k+1) half2 per n column; one STS.128
        {
            __half2 b0 = __floats2half2_rn(rb0.x, rb1.x);
            __half2 b1 = __floats2half2_rn(rb0.y, rb1.y);
            __half2 b2 = __floats2half2_rn(rb0.z, rb1.z);
            __half2 b3 = __floats2half2_rn(rb0.w, rb1.w);
            uint4 pk;
            pk.x = *reinterpret_cast<unsigned int*>(&b0);
            pk.y = *reinterpret_cast<unsigned int*>(&b1);
            pk.z = *reinterpret_cast<unsigned int*>(&b2);
            pk.w = *reinterpret_cast<unsigned int*>(&b3);
            *reinterpret_cast<uint4*>(&Bs2[bkp][bnc]) = pk;
        }
        __syncthreads();   // tiles visible

        if (c + 1 < NCHUNK) {
            const int kn = (c + 1) * TK;
            ra0 = *reinterpret_cast<const float4*>(&A[(bm + ar0) * NS + kn + ac0]);
            ra1 = *reinterpret_cast<const float4*>(&A[(bm + ar1) * NS + kn + ac1]);
            rb0 = *reinterpret_cast<const float4*>(&B[(kn + 2 * bkp    ) * NS + bn + bnc]);
            rb1 = *reinterpret_cast<const float4*>(&B[(kn + 2 * bkp + 1) * NS + bn + bnc]);
        }

#pragma unroll
        for (int kp = 0; kp < KP; ++kp) {
            const __half2 a0 = As2[m0 + 0][kp];
            const __half2 a1 = As2[m0 + 1][kp];
            const __half2 a2 = As2[m0 + 2][kp];
            const __half2 a3 = As2[m0 + 3][kp];

            const uint4 bv = *reinterpret_cast<const uint4*>(&Bs2[kp][n0]);
            const __half2 b0 = *reinterpret_cast<const __half2*>(&bv.x);
            const __half2 b1 = *reinterpret_cast<const __half2*>(&bv.y);
            const __half2 b2 = *reinterpret_cast<const __half2*>(&bv.z);
            const __half2 b3 = *reinterpret_cast<const __half2*>(&bv.w);

            acc[0][0] = __hmax2(acc[0][0], __hmin2(a0, b0));
            acc[0][1] = __hmax2(acc[0][1], __hmin2(a0, b1));
            acc[0][2] = __hmax2(acc[0][2], __hmin2(a0, b2));
            acc[0][3] = __hmax2(acc[0][3], __hmin2(a0, b3));

            acc[1][0] = __hmax2(acc[1][0], __hmin2(a1, b0));
            acc[1][1] = __hmax2(acc[1][1], __hmin2(a1, b1));
            acc[1][2] = __hmax2(acc[1][2], __hmin2(a1, b2));
            acc[1][3] = __hmax2(acc[1][3], __hmin2(a1, b3));

            acc[2][0] = __hmax2(acc[2][0], __hmin2(a2, b0));
            acc[2][1] = __hmax2(acc[2][1], __hmin2(a2, b1));
            acc[2][2] = __hmax2(acc[2][2], __hmin2(a2, b2));
            acc[2][3] = __hmax2(acc[2][3], __hmin2(a2, b3));

            acc[3][0] = __hmax2(acc[3][0], __hmin2(a3, b0));
            acc[3][1] = __hmax2(acc[3][1], __hmin2(a3, b1));
            acc[3][2] = __hmax2(acc[3][2], __hmin2(a3, b2));
            acc[3][3] = __hmax2(acc[3][3], __hmin2(a3, b3));
        }
    }

    // ---- epilogue: fold k-pair lanes, then out = t + num*(1 - t), t = t[comp] ----
    float* __restrict__ O = out + comp * (NS * NS);
#pragma unroll
    for (int i = 0; i < 4; ++i) {
        const int row = bm + m0 + i;
        const float4 tv = *reinterpret_cast<const float4*>(&B[row * NS + bn + n0]);
        float4 r;
        {
            const float n00 = fmaxf(__low2float(acc[i][0]), __high2float(acc[i][0]));
            const float n01 = fmaxf(__low2float(acc[i][1]), __high2float(acc[i][1]));
            const float n02 = fmaxf(__low2float(acc[i][2]), __high2float(acc[i][2]));
            const float n03 = fmaxf(__low2float(acc[i][3]), __high2float(acc[i][3]));
            r.x = tv.x + n00 * (1.0f - tv.x);
            r.y = tv.y + n01 * (1.0f - tv.y);
            r.z = tv.z + n02 * (1.0f - tv.z);
            r.w = tv.w + n03 * (1.0f - tv.w);
        }
        *reinterpret_cast<float4*>(&O[row * NS + bn + n0]) = r;
    }
}

} // namespace

extern "C" void kernel_launch(void* const* d_in, const int* in_sizes, int n_in,
                              void* d_out, int out_size)
{
    (void)in_sizes; (void)n_in; (void)out_size;
    const float* t = reinterpret_cast<const float*>(d_in[0]);
    float* out     = reinterpret_cast<float*>(d_out);

    dim3 grid(NS / TN, NS / TM, 2);   // 8 x 8 x 2 = 128 blocks
    fuzzy_compose_h2_kernel<<<grid, THREADS>>>(t, out);
}